// round 2
// baseline (speedup 1.0000x reference)
#include <cuda_runtime.h>

#define N_TOK 65536
#define D 256
#define K 1024
#define B_ 16
#define HW 4096

typedef unsigned long long ull;

__device__ float g_sz[N_TOK];   // ||z_n||^2
__device__ float g_en[K];       // ||e_k||^2
__device__ int   g_idx[N_TOK];  // argmin indices

// Packed dual-fp32 FMA (sm_103a FFMA2) — only reachable via PTX f32x2.
__device__ __forceinline__ void ffma2(ull& acc, ull a, ull b) {
    asm("fma.rn.f32x2 %0, %1, %2, %3;" : "=l"(acc) : "l"(a), "l"(b), "l"(acc));
}
__device__ __forceinline__ ull dup2(float v) {
    ull r; asm("mov.b64 %0, {%1, %1};" : "=l"(r) : "f"(v)); return r;
}

// ---------------------------------------------------------------------------
// ||z_n||^2 straight from NCHW (coalesced: warp spans consecutive hw)
// ---------------------------------------------------------------------------
__global__ void k_sz(const float* __restrict__ z) {
    int n = blockIdx.x * 256 + threadIdx.x;
    int b = n >> 12, hw = n & (HW - 1);
    const float* p = z + (size_t)b * D * HW + hw;
    float s = 0.f;
#pragma unroll 4
    for (int c = 0; c < D; c++) { float v = p[(size_t)c * HW]; s = fmaf(v, v, s); }
    g_sz[n] = s;
}

// ---------------------------------------------------------------------------
// ||e_k||^2 (one warp per code)
// ---------------------------------------------------------------------------
__global__ void k_en(const float* __restrict__ emb) {
    int w = (blockIdx.x * blockDim.x + threadIdx.x) >> 5;
    int lane = threadIdx.x & 31;
    const float4* row = (const float4*)(emb + (size_t)w * D);
    float s = 0.f;
#pragma unroll
    for (int i = 0; i < 2; i++) {
        float4 v = row[lane + 32 * i];
        s += v.x * v.x + v.y * v.y + v.z * v.z + v.w * v.w;
    }
#pragma unroll
    for (int o = 16; o; o >>= 1) s += __shfl_down_sync(0xFFFFFFFFu, s, o);
    if (lane == 0) g_en[w] = s;
}

// ---------------------------------------------------------------------------
// Distances + argmin. 128 tokens x 128 codes per block, FFMA2 inner loop.
// Per-thread: 8 m (4 packed pairs) x 8 k. A read directly from NCHW z.
// d = fl(fl(Sz+en) - 2*dot), sequential-d fp32 accumulation, first-index ties.
// ---------------------------------------------------------------------------
__global__ __launch_bounds__(256, 2) void k_dist(const float* __restrict__ z,
                                                 const float* __restrict__ emb) {
    __shared__ union {
        struct { float As[16][128]; float Bs2[16][256]; } mm;  // Bs2 = duplicated pairs
        struct { float RD[128][17]; int RK[128][17]; } red;
    } sm;
    __shared__ float sEn[K];
    __shared__ float sSz[128];

    int tid = threadIdx.x;
    int tx = tid & 15, ty = tid >> 4;
    int m0  = blockIdx.x * 128;
    int b   = m0 >> 12;
    int hw0 = m0 & (HW - 1);

    for (int i = tid; i < K; i += 256) sEn[i] = g_en[i];
    if (tid < 128) sSz[tid] = g_sz[m0 + tid];

    int ldd  = tid >> 4;          // A stage: d row (0..15)
    int lcol = (tid & 15) * 8;    // A stage: token col
    int brow = tid >> 1;          // B stage: code row (0..127)
    int bh   = (tid & 1) * 8;     // B stage: d offset

    const float* zbase = z + (size_t)b * D * HW + hw0;

    float bestd[8]; int bestk[8];
#pragma unroll
    for (int i = 0; i < 8; i++) { bestd[i] = 3.4e38f; bestk[i] = 0; }

    for (int kk = 0; kk < K; kk += 128) {
        ull acc[4][8];
#pragma unroll
        for (int p = 0; p < 4; p++)
#pragma unroll
            for (int j = 0; j < 8; j++) acc[p][j] = 0ull;

        for (int d0 = 0; d0 < D; d0 += 16) {
            // gmem loads (coalesced): A row from z NCHW, B row from emb
            float4 a0 = *(const float4*)(zbase + (size_t)(d0 + ldd) * HW + lcol);
            float4 a1 = *(const float4*)(zbase + (size_t)(d0 + ldd) * HW + lcol + 4);
            float4 e0 = *(const float4*)(emb + (size_t)(kk + brow) * D + d0 + bh);
            float4 e1 = *(const float4*)(emb + (size_t)(kk + brow) * D + d0 + bh + 4);
            __syncthreads();   // previous tile fully consumed
            *(float4*)&sm.mm.As[ldd][lcol]     = a0;
            *(float4*)&sm.mm.As[ldd][lcol + 4] = a1;
            {
                float fv[8] = {e0.x, e0.y, e0.z, e0.w, e1.x, e1.y, e1.z, e1.w};
#pragma unroll
                for (int q = 0; q < 8; q++)
                    *(ull*)&sm.mm.Bs2[bh + q][2 * brow] = dup2(fv[q]);
            }
            __syncthreads();
#pragma unroll
            for (int dd = 0; dd < 16; dd++) {
                ulonglong2 av0 = *(const ulonglong2*)&sm.mm.As[dd][ty * 8];
                ulonglong2 av1 = *(const ulonglong2*)&sm.mm.As[dd][ty * 8 + 4];
                ulonglong2 bq0 = *(const ulonglong2*)&sm.mm.Bs2[dd][tx * 16];
                ulonglong2 bq1 = *(const ulonglong2*)&sm.mm.Bs2[dd][tx * 16 + 4];
                ulonglong2 bq2 = *(const ulonglong2*)&sm.mm.Bs2[dd][tx * 16 + 8];
                ulonglong2 bq3 = *(const ulonglong2*)&sm.mm.Bs2[dd][tx * 16 + 12];
                ull a2[4] = {av0.x, av0.y, av1.x, av1.y};
                ull b2[8] = {bq0.x, bq0.y, bq1.x, bq1.y, bq2.x, bq2.y, bq3.x, bq3.y};
#pragma unroll
                for (int p = 0; p < 4; p++)
#pragma unroll
                    for (int j = 0; j < 8; j++)
                        ffma2(acc[p][j], a2[p], b2[j]);
            }
        }

        // epilogue: fold this code-tile into running argmin (k ascending)
#pragma unroll
        for (int j = 0; j < 8; j++) {
            int k = kk + tx * 8 + j;
            float en = sEn[k];
#pragma unroll
            for (int p = 0; p < 4; p++) {
                float lo = __uint_as_float((unsigned)(acc[p][j] & 0xFFFFFFFFu));
                float hi = __uint_as_float((unsigned)(acc[p][j] >> 32));
                int mlo = ty * 8 + 2 * p;
                float slo = sSz[mlo] + en;
                float dlo = slo - 2.0f * lo;
                if (dlo < bestd[2 * p]) { bestd[2 * p] = dlo; bestk[2 * p] = k; }
                float shi = sSz[mlo + 1] + en;
                float dhi = shi - 2.0f * hi;
                if (dhi < bestd[2 * p + 1]) { bestd[2 * p + 1] = dhi; bestk[2 * p + 1] = k; }
            }
        }
    }

    // cross-thread reduction over tx per token row
    __syncthreads();
#pragma unroll
    for (int i = 0; i < 8; i++) {
        sm.red.RD[ty * 8 + i][tx] = bestd[i];
        sm.red.RK[ty * 8 + i][tx] = bestk[i];
    }
    __syncthreads();
    if (tid < 128) {
        float bd = 3.4e38f;
        int   bk = 0x7FFFFFFF;
#pragma unroll
        for (int c = 0; c < 16; c++) {
            float v  = sm.red.RD[tid][c];
            int   k2 = sm.red.RK[tid][c];
            if (v < bd || (v == bd && k2 < bk)) { bd = v; bk = k2; }
        }
        g_idx[m0 + tid] = bk;
    }
}

// ---------------------------------------------------------------------------
// indices as float (tuple element 0)
// ---------------------------------------------------------------------------
__global__ void k_out_idx(float* __restrict__ out) {
    int n = blockIdx.x * blockDim.x + threadIdx.x;
    out[n] = (float)g_idx[n];
}

// ---------------------------------------------------------------------------
// gather z_q back to NCHW (coalesced writes)
// ---------------------------------------------------------------------------
__global__ void k_out_zq(const float* __restrict__ emb, float* __restrict__ out) {
    int t  = blockIdx.x * blockDim.x + threadIdx.x;   // over B*D*HW
    int hw = t & (HW - 1);
    int c  = (t >> 12) & (D - 1);
    int b  = t >> 20;
    int idx = g_idx[b * HW + hw];
    out[t] = emb[idx * D + c];
}

// ---------------------------------------------------------------------------
extern "C" void kernel_launch(void* const* d_in, const int* in_sizes, int n_in,
                              void* d_out, int out_size) {
    const float* z   = (const float*)d_in[0];
    const float* emb = (const float*)d_in[1];
    float* out = (float*)d_out;

    k_sz<<<N_TOK / 256, 256>>>(z);
    k_en<<<K / 8, 256>>>(emb);
    k_dist<<<N_TOK / 128, 256>>>(z, emb);
    k_out_idx<<<N_TOK / 256, 256>>>(out);
    k_out_zq<<<(B_ * D * HW) / 256, 256>>>(emb, out + N_TOK);
}

// round 10
// speedup vs baseline: 1.9474x; 1.9474x over previous
#include <cuda_runtime.h>
#include <cuda_bf16.h>
#include <cstdint>

#define N_TOK 65536
#define D 256
#define K 1024
#define HW 4096
#define CAP 16

__device__ float g_sz[N_TOK];
__device__ float g_en[K];
__device__ int   g_idx[N_TOK];
__device__ __align__(16) __nv_bfloat16 g_eb1[K * D];
__device__ __align__(16) __nv_bfloat16 g_eb2[K * D];
__device__ int g_cand[N_TOK * CAP];
__device__ int g_ncand[N_TOK];
__device__ int g_flag[N_TOK];
__device__ int g_nflag;

__device__ __forceinline__ uint32_t smem_u32(const void* p) {
    uint32_t a;
    asm("{ .reg .u64 t; cvta.to.shared.u64 t, %1; cvt.u32.u64 %0, t; }" : "=r"(a) : "l"(p));
    return a;
}
__device__ __forceinline__ void cp16(uint32_t s, const void* g) {
    asm volatile("cp.async.ca.shared.global [%0], [%1], 16;" :: "r"(s), "l"(g));
}
__device__ __forceinline__ void ldm_x4(uint32_t* r, uint32_t a) {
    asm volatile("ldmatrix.sync.aligned.m8n8.x4.shared.b16 {%0,%1,%2,%3}, [%4];"
        : "=r"(r[0]), "=r"(r[1]), "=r"(r[2]), "=r"(r[3]) : "r"(a));
}
__device__ __forceinline__ void ldm_x2(uint32_t* r, uint32_t a) {
    asm volatile("ldmatrix.sync.aligned.m8n8.x2.shared.b16 {%0,%1}, [%2];"
        : "=r"(r[0]), "=r"(r[1]) : "r"(a));
}
__device__ __forceinline__ void mma_bf16(float* c, const uint32_t* a, const uint32_t* b) {
    asm volatile("mma.sync.aligned.m16n8k16.row.col.f32.bf16.bf16.f32 "
        "{%0,%1,%2,%3}, {%4,%5,%6,%7}, {%8,%9}, {%0,%1,%2,%3};"
        : "+f"(c[0]), "+f"(c[1]), "+f"(c[2]), "+f"(c[3])
        : "r"(a[0]), "r"(a[1]), "r"(a[2]), "r"(a[3]), "r"(b[0]), "r"(b[1]));
}
__device__ __forceinline__ uint32_t mono(float f) {
    uint32_t u = __float_as_uint(f);
    return (u & 0x80000000u) ? ~u : (u | 0x80000000u);
}
__device__ __forceinline__ float demono(uint32_t u) {
    return (u & 0x80000000u) ? __uint_as_float(u ^ 0x80000000u) : __uint_as_float(~u);
}

__global__ void k_init() { if (threadIdx.x == 0) g_nflag = 0; }

__global__ void k_sz(const float* __restrict__ z) {
    int n = blockIdx.x * 256 + threadIdx.x;
    int b = n >> 12, hw = n & (HW - 1);
    const float* p = z + (size_t)b * D * HW + hw;
    float s = 0.f;
#pragma unroll 4
    for (int c = 0; c < D; c++) { float v = p[(size_t)c * HW]; s = fmaf(v, v, s); }
    g_sz[n] = s;
}
__global__ void k_en(const float* __restrict__ emb) {
    int w = (blockIdx.x * blockDim.x + threadIdx.x) >> 5;
    int lane = threadIdx.x & 31;
    const float4* row = (const float4*)(emb + (size_t)w * D);
    float s = 0.f;
#pragma unroll
    for (int i = 0; i < 2; i++) {
        float4 v = row[lane + 32 * i];
        s += v.x * v.x + v.y * v.y + v.z * v.z + v.w * v.w;
    }
#pragma unroll
    for (int o = 16; o; o >>= 1) s += __shfl_down_sync(0xFFFFFFFFu, s, o);
    if (lane == 0) g_en[w] = s;
}
__global__ void k_prep(const float* __restrict__ emb) {
    int i = blockIdx.x * 256 + threadIdx.x;
    float v = emb[i];
    __nv_bfloat16 h = __float2bfloat16(v);
    g_eb1[i] = h;
    g_eb2[i] = __float2bfloat16(v - __bfloat162float(h));
}

// ---- pass 1: bf16 mma.sync scores, per-token window candidates -------------
#define A1_O 0u
#define A2_O 32768u
#define B_O  65536u
#define EN_O 196608u
#define BEST_O 200704u
#define CNT_O 201216u
#define FLG_O 201472u
#define LIST_O 201728u
#define SM1 205824u

__global__ __launch_bounds__(256) void k_pass1(const float* __restrict__ z) {
    extern __shared__ char sm[];
    const uint32_t sb = smem_u32(sm);
    int tid = threadIdx.x, lane = tid & 31, w = tid >> 5;
    int wm = w & 1, wn = w >> 1, gid = lane >> 2, qid = lane & 3;
    int m0 = blockIdx.x * 64;
    int bz = m0 >> 12, hw0 = m0 & (HW - 1);
    const float* zb = z + (size_t)bz * D * HW + hw0;
    float* sEn = (float*)(sm + EN_O);
    unsigned long long* sBest = (unsigned long long*)(sm + BEST_O);
    unsigned* sCnt = (unsigned*)(sm + CNT_O);
    unsigned* sFlg = (unsigned*)(sm + FLG_O);
    int* sList = (int*)(sm + LIST_O);

    for (int i = tid; i < K; i += 256) sEn[i] = g_en[i];
    if (tid < 64) { sBest[tid] = ~0ull; sCnt[tid] = 0u; sFlg[tid] = 0u; }
    // stage A (full-K resident, hi/lo split, swizzled)
#pragma unroll 4
    for (int i = 0; i < 64; i++) {
        int id = i * 256 + tid;
        int d = id >> 6, r = id & 63;
        float v = zb[(size_t)d * HW + r];
        __nv_bfloat16 h = __float2bfloat16(v);
        __nv_bfloat16 l = __float2bfloat16(v - __bfloat162float(h));
        uint32_t off = (uint32_t)(r * 512 + (((d >> 3) ^ (r & 7)) * 16) + (d & 7) * 2);
        *(__nv_bfloat16*)(sm + A1_O + off) = h;
        *(__nv_bfloat16*)(sm + A2_O + off) = l;
    }
    auto stageB = [&](int t, int buf) {
        int kk = t * 64;
#pragma unroll
        for (int i = 0; i < 16; i++) {
            int id = i * 256 + tid;
            int split = id >> 11, rem = id & 2047, row = rem >> 5, c = rem & 31;
            const __nv_bfloat16* src = (split ? g_eb2 : g_eb1) + (size_t)(kk + row) * 256 + c * 8;
            uint32_t dst = sb + B_O + (uint32_t)buf * 65536u + (uint32_t)split * 32768u
                         + (uint32_t)(row * 512 + ((c ^ (row & 7)) * 16));
            cp16(dst, src);
        }
        asm volatile("cp.async.commit_group;" ::: "memory");
    };
    stageB(0, 0);

    float bd1[4], bd2[4]; int bk1[4], bk2[4];
#pragma unroll
    for (int i = 0; i < 4; i++) { bd1[i] = bd2[i] = 3.4e38f; bk1[i] = bk2[i] = 0; }

    for (int t = 0; t < 16; t++) {
        if (t < 15) { stageB(t + 1, (t + 1) & 1);
                      asm volatile("cp.async.wait_group 1;" ::: "memory"); }
        else        { asm volatile("cp.async.wait_group 0;" ::: "memory"); }
        __syncthreads();
        uint32_t Bb = sb + B_O + (uint32_t)(t & 1) * 65536u;
        float acc[2][2][4];
#pragma unroll
        for (int mt = 0; mt < 2; mt++)
#pragma unroll
            for (int nt = 0; nt < 2; nt++)
#pragma unroll
                for (int c = 0; c < 4; c++) acc[mt][nt][c] = 0.f;
#pragma unroll
        for (int ks = 0; ks < 16; ks++) {
            uint32_t a1f[2][4], a2f[2][4], b1f[2][2], b2f[2][2];
#pragma unroll
            for (int mt = 0; mt < 2; mt++) {
                int row = wm * 32 + mt * 16 + (lane & 15);
                uint32_t off = (uint32_t)(row * 512 + (((ks * 2 + (lane >> 4)) ^ (row & 7)) * 16));
                ldm_x4(a1f[mt], sb + A1_O + off);
                ldm_x4(a2f[mt], sb + A2_O + off);
            }
#pragma unroll
            for (int nt = 0; nt < 2; nt++) {
                int row = wn * 16 + nt * 8 + (lane & 7);
                uint32_t off = (uint32_t)(row * 512 + (((ks * 2 + ((lane >> 3) & 1)) ^ (row & 7)) * 16));
                ldm_x2(b1f[nt], Bb + off);
                ldm_x2(b2f[nt], Bb + 32768u + off);
            }
#pragma unroll
            for (int mt = 0; mt < 2; mt++)
#pragma unroll
                for (int nt = 0; nt < 2; nt++) {
                    mma_bf16(acc[mt][nt], a1f[mt], b1f[nt]);
                    mma_bf16(acc[mt][nt], a1f[mt], b2f[nt]);
                    mma_bf16(acc[mt][nt], a2f[mt], b1f[nt]);
                }
        }
#pragma unroll
        for (int mt = 0; mt < 2; mt++)
#pragma unroll
            for (int nt = 0; nt < 2; nt++)
#pragma unroll
                for (int c = 0; c < 4; c++) {
                    int kg = t * 64 + wn * 16 + nt * 8 + qid * 2 + (c & 1);
                    float sv = fmaf(-2.f, acc[mt][nt][c], sEn[kg]);
                    int rs = mt * 2 + (c >> 1);
                    if (sv < bd1[rs]) { bd2[rs] = bd1[rs]; bk2[rs] = bk1[rs];
                                        bd1[rs] = sv;      bk1[rs] = kg; }
                    else if (sv < bd2[rs]) { bd2[rs] = sv; bk2[rs] = kg; }
                }
        __syncthreads();
    }
#pragma unroll
    for (int rs = 0; rs < 4; rs++) {
        int r = wm * 32 + (rs >> 1) * 16 + gid + 8 * (rs & 1);
        unsigned long long pk = ((unsigned long long)mono(bd1[rs]) << 32) | (unsigned)bk1[rs];
        atomicMin(&sBest[r], pk);
    }
    __syncthreads();
#pragma unroll
    for (int rs = 0; rs < 4; rs++) {
        int r = wm * 32 + (rs >> 1) * 16 + gid + 8 * (rs & 1);
        float thr = demono((uint32_t)(sBest[r] >> 32)) + 2e-4f + 2e-6f * g_sz[m0 + r];
        if (bd1[rs] <= thr) {
            unsigned o = atomicAdd(&sCnt[r], 1u);
            if (o < CAP) sList[r * CAP + o] = bk1[rs];
        }
        if (bd2[rs] <= thr) {   // thread's top-2 both in window: unsafe
            unsigned o = atomicAdd(&sCnt[r], 1u);
            if (o < CAP) sList[r * CAP + o] = bk2[rs];
            sFlg[r] = 1u;
        }
    }
    __syncthreads();
    if (tid < 64) {
        int n = m0 + tid; unsigned nc = sCnt[tid];
        if (sFlg[tid] || nc > CAP) {
            int p = atomicAdd(&g_nflag, 1); g_flag[p] = n; g_ncand[n] = -1;
        } else {
            g_ncand[n] = (int)nc;
            for (unsigned i = 0; i < nc; i++) g_cand[n * CAP + i] = sList[tid * CAP + i];
        }
    }
}

// ---- pass 2: exact rescore (R1-proven comparator) --------------------------
__global__ __launch_bounds__(256) void k_rescore(const float* __restrict__ z,
                                                 const float* __restrict__ emb) {
    extern __shared__ float zs[];   // [64][257]
    int tid = threadIdx.x;
    int m0 = blockIdx.x * 64;
    int bz = m0 >> 12, hw0 = m0 & (HW - 1);
    const float* zb = z + (size_t)bz * D * HW + hw0;
#pragma unroll 4
    for (int i = 0; i < 64; i++) {
        int id = i * 256 + tid;
        int d = id >> 6, r = id & 63;
        zs[r * 257 + d] = zb[(size_t)d * HW + r];
    }
    __syncthreads();
    if (tid < 64) {
        int n = m0 + tid;
        int nc = g_ncand[n];
        if (nc >= 0) {
            float szn = g_sz[n];
            const float* zr = zs + tid * 257;
            float best = 3.4e38f; int bk = 0x7fffffff;
            for (int i = 0; i < nc; i++) {
                int k = g_cand[n * CAP + i];
                const float* er = emb + (size_t)k * D;
                float a = 0.f;
                for (int d = 0; d < D; d++) a = fmaf(zr[d], er[d], a);
                float s1 = szn + g_en[k];
                float dv = fmaf(-2.f, a, s1);
                if (dv < best || (dv == best && k < bk)) { best = dv; bk = k; }
            }
            g_idx[n] = bk;
        }
    }
}

// ---- fallback: full exact scan for flagged tokens --------------------------
__global__ __launch_bounds__(256) void k_fb(const float* __restrict__ z,
                                            const float* __restrict__ emb) {
    __shared__ float zr[256];
    __shared__ unsigned long long red[256];
    int tid = threadIdx.x;
    int nf = g_nflag;
    for (int f = blockIdx.x; f < nf; f += gridDim.x) {
        int n = g_flag[f];
        int bz = n >> 12, hw = n & (HW - 1);
        zr[tid] = z[((size_t)bz * D + tid) * HW + hw];
        __syncthreads();
        float szn = g_sz[n];
        unsigned long long bp = ~0ull;
        for (int j = 0; j < 4; j++) {
            int k = tid + 256 * j;
            const float* er = emb + (size_t)k * D;
            float a = 0.f;
            for (int d = 0; d < D; d++) a = fmaf(zr[d], er[d], a);
            float s1 = szn + g_en[k];
            float dv = fmaf(-2.f, a, s1);
            unsigned long long pk = ((unsigned long long)mono(dv) << 32) | (unsigned)k;
            if (pk < bp) bp = pk;
        }
        red[tid] = bp;
        __syncthreads();
        if (tid == 0) {
            unsigned long long m = red[0];
            for (int i = 1; i < 256; i++) if (red[i] < m) m = red[i];
            g_idx[n] = (int)(m & 0xffffffffu);
        }
        __syncthreads();
    }
}

// ---- outputs ----------------------------------------------------------------
__global__ void k_out_idx(float* __restrict__ out) {
    int n = blockIdx.x * blockDim.x + threadIdx.x;
    out[n] = (float)g_idx[n];
}
__global__ void k_out_zq(const float* __restrict__ emb, float* __restrict__ out) {
    int t = blockIdx.x * blockDim.x + threadIdx.x;
    int hw = t & (HW - 1);
    int c = (t >> 12) & (D - 1);
    int b = t >> 20;
    out[t] = emb[g_idx[b * HW + hw] * D + c];
}

extern "C" void kernel_launch(void* const* d_in, const int* in_sizes, int n_in,
                              void* d_out, int out_size) {
    const float* z   = (const float*)d_in[0];
    const float* emb = (const float*)d_in[1];
    float* out = (float*)d_out;

    cudaFuncSetAttribute(k_pass1, cudaFuncAttributeMaxDynamicSharedMemorySize, SM1);
    cudaFuncSetAttribute(k_rescore, cudaFuncAttributeMaxDynamicSharedMemorySize, 64 * 257 * 4);

    k_init<<<1, 32>>>();
    k_sz<<<N_TOK / 256, 256>>>(z);
    k_en<<<K / 8, 256>>>(emb);
    k_prep<<<K * D / 256, 256>>>(emb);
    k_pass1<<<N_TOK / 64, 256, SM1>>>(z);
    k_rescore<<<N_TOK / 64, 256, 64 * 257 * 4>>>(z, emb);
    k_fb<<<256, 256>>>(z, emb);
    k_out_idx<<<N_TOK / 256, 256>>>(out);
    k_out_zq<<<(16 * D * HW) / 256, 256>>>(emb, out + N_TOK);
}

// round 11
// speedup vs baseline: 3.7528x; 1.9271x over previous
#include <cuda_runtime.h>
#include <cuda_fp16.h>
#include <cstdint>

#define N_TOK 65536
#define D 256
#define K 1024
#define HW 4096
#define CAP 16

__device__ float g_sz[N_TOK];
__device__ float g_en[K];
__device__ int   g_idx[N_TOK];
__device__ __align__(16) __half g_ef[K * D];
__device__ int g_cand[N_TOK * CAP];
__device__ int g_ncand[N_TOK];
__device__ int g_flag[N_TOK];
__device__ int g_nflag;

__device__ __forceinline__ uint32_t smem_u32(const void* p) {
    uint32_t a;
    asm("{ .reg .u64 t; cvta.to.shared.u64 t, %1; cvt.u32.u64 %0, t; }" : "=r"(a) : "l"(p));
    return a;
}
__device__ __forceinline__ void cp16(uint32_t s, const void* g) {
    asm volatile("cp.async.ca.shared.global [%0], [%1], 16;" :: "r"(s), "l"(g));
}
__device__ __forceinline__ void ldm_x4(uint32_t* r, uint32_t a) {
    asm volatile("ldmatrix.sync.aligned.m8n8.x4.shared.b16 {%0,%1,%2,%3}, [%4];"
        : "=r"(r[0]), "=r"(r[1]), "=r"(r[2]), "=r"(r[3]) : "r"(a));
}
__device__ __forceinline__ void ldm_x2(uint32_t* r, uint32_t a) {
    asm volatile("ldmatrix.sync.aligned.m8n8.x2.shared.b16 {%0,%1}, [%2];"
        : "=r"(r[0]), "=r"(r[1]) : "r"(a));
}
__device__ __forceinline__ void mma_f16(float* c, const uint32_t* a, const uint32_t* b) {
    asm volatile("mma.sync.aligned.m16n8k16.row.col.f32.f16.f16.f32 "
        "{%0,%1,%2,%3}, {%4,%5,%6,%7}, {%8,%9}, {%0,%1,%2,%3};"
        : "+f"(c[0]), "+f"(c[1]), "+f"(c[2]), "+f"(c[3])
        : "r"(a[0]), "r"(a[1]), "r"(a[2]), "r"(a[3]), "r"(b[0]), "r"(b[1]));
}
__device__ __forceinline__ uint32_t mono(float f) {
    uint32_t u = __float_as_uint(f);
    return (u & 0x80000000u) ? ~u : (u | 0x80000000u);
}
__device__ __forceinline__ float demono(uint32_t u) {
    return (u & 0x80000000u) ? __uint_as_float(u ^ 0x80000000u) : __uint_as_float(~u);
}

__global__ void k_init() { if (threadIdx.x == 0) g_nflag = 0; }

__global__ void k_sz(const float* __restrict__ z) {   // exact (R1-proven)
    int n = blockIdx.x * 256 + threadIdx.x;
    int b = n >> 12, hw = n & (HW - 1);
    const float* p = z + (size_t)b * D * HW + hw;
    float s = 0.f;
#pragma unroll 4
    for (int c = 0; c < D; c++) { float v = p[(size_t)c * HW]; s = fmaf(v, v, s); }
    g_sz[n] = s;
}
__global__ void k_en(const float* __restrict__ emb) { // exact (R1-proven)
    int w = (blockIdx.x * blockDim.x + threadIdx.x) >> 5;
    int lane = threadIdx.x & 31;
    const float4* row = (const float4*)(emb + (size_t)w * D);
    float s = 0.f;
#pragma unroll
    for (int i = 0; i < 2; i++) {
        float4 v = row[lane + 32 * i];
        s += v.x * v.x + v.y * v.y + v.z * v.z + v.w * v.w;
    }
#pragma unroll
    for (int o = 16; o; o >>= 1) s += __shfl_down_sync(0xFFFFFFFFu, s, o);
    if (lane == 0) g_en[w] = s;
}
__global__ void k_prep(const float* __restrict__ emb) {
    int i = blockIdx.x * 256 + threadIdx.x;
    g_ef[i] = __float2half(emb[i]);
}

// ---- pass 1: single-product fp16 mma scores + sound candidate windows ------
#define A_O    0u
#define B_O    32768u
#define EN_O   98304u
#define BEST_O 102400u
#define CNT_O  102912u
#define FLG_O  103168u
#define LIST_O 103424u
#define SM1    107520u

__global__ __launch_bounds__(256) void k_pass1(const float* __restrict__ z) {
    extern __shared__ char sm[];
    const uint32_t sb = smem_u32(sm);
    int tid = threadIdx.x, lane = tid & 31, w = tid >> 5;
    int wm = w & 1, wn = w >> 1, gid = lane >> 2, qid = lane & 3;
    int m0 = blockIdx.x * 64;
    int bz = m0 >> 12, hw0 = m0 & (HW - 1);
    const float* zb = z + (size_t)bz * D * HW + hw0;
    float* sEn = (float*)(sm + EN_O);
    unsigned long long* sBest = (unsigned long long*)(sm + BEST_O);
    unsigned* sCnt = (unsigned*)(sm + CNT_O);
    unsigned* sFlg = (unsigned*)(sm + FLG_O);
    int* sList = (int*)(sm + LIST_O);

    for (int i = tid; i < K; i += 256) sEn[i] = g_en[i];
    if (tid < 64) { sBest[tid] = ~0ull; sCnt[tid] = 0u; sFlg[tid] = 0u; }
    // stage A: 64 tokens x 256 dims fp16 (full-K resident, swizzled)
#pragma unroll 4
    for (int i = 0; i < 64; i++) {
        int id = i * 256 + tid;
        int d = id >> 6, r = id & 63;
        float v = zb[(size_t)d * HW + r];
        uint32_t off = (uint32_t)(r * 512 + (((d >> 3) ^ (r & 7)) * 16) + (d & 7) * 2);
        *(__half*)(sm + A_O + off) = __float2half(v);
    }
    auto stageB = [&](int t, int buf) {   // 64 codes x 256 dims fp16
        int kk = t * 64;
#pragma unroll
        for (int i = 0; i < 8; i++) {
            int id = i * 256 + tid;
            int row = id >> 5, c = id & 31;
            cp16(sb + B_O + (uint32_t)buf * 32768u +
                     (uint32_t)(row * 512 + ((c ^ (row & 7)) * 16)),
                 g_ef + (size_t)(kk + row) * 256 + c * 8);
        }
        asm volatile("cp.async.commit_group;" ::: "memory");
    };
    stageB(0, 0);
    __syncthreads();

    float bd1[4], bd2[4]; int bk1[4], bk2[4];
#pragma unroll
    for (int i = 0; i < 4; i++) { bd1[i] = bd2[i] = 3.4e38f; bk1[i] = bk2[i] = 0; }

    for (int t = 0; t < 16; t++) {
        if (t < 15) { stageB(t + 1, (t + 1) & 1);
                      asm volatile("cp.async.wait_group 1;" ::: "memory"); }
        else        { asm volatile("cp.async.wait_group 0;" ::: "memory"); }
        __syncthreads();
        uint32_t Bb = sb + B_O + (uint32_t)(t & 1) * 32768u;
        float acc[2][2][4];
#pragma unroll
        for (int mt = 0; mt < 2; mt++)
#pragma unroll
            for (int nt = 0; nt < 2; nt++)
#pragma unroll
                for (int c = 0; c < 4; c++) acc[mt][nt][c] = 0.f;
#pragma unroll
        for (int ks = 0; ks < 16; ks++) {
            uint32_t af[2][4], bf[2][2];
#pragma unroll
            for (int mt = 0; mt < 2; mt++) {
                int row = wm * 32 + mt * 16 + (lane & 15);
                ldm_x4(af[mt], sb + A_O +
                    (uint32_t)(row * 512 + (((ks * 2 + (lane >> 4)) ^ (row & 7)) * 16)));
            }
#pragma unroll
            for (int nt = 0; nt < 2; nt++) {
                int row = wn * 16 + nt * 8 + (lane & 7);
                ldm_x2(bf[nt], Bb +
                    (uint32_t)(row * 512 + (((ks * 2 + ((lane >> 3) & 1)) ^ (row & 7)) * 16)));
            }
#pragma unroll
            for (int mt = 0; mt < 2; mt++)
#pragma unroll
                for (int nt = 0; nt < 2; nt++)
                    mma_f16(acc[mt][nt], af[mt], bf[nt]);
        }
#pragma unroll
        for (int mt = 0; mt < 2; mt++)
#pragma unroll
            for (int nt = 0; nt < 2; nt++)
#pragma unroll
                for (int c = 0; c < 4; c++) {
                    int kg = t * 64 + wn * 16 + nt * 8 + qid * 2 + (c & 1);
                    float sv = fmaf(-2.f, acc[mt][nt][c], sEn[kg]);
                    int rs = mt * 2 + (c >> 1);
                    if (sv < bd1[rs]) { bd2[rs] = bd1[rs]; bk2[rs] = bk1[rs];
                                        bd1[rs] = sv;      bk1[rs] = kg; }
                    else if (sv < bd2[rs]) { bd2[rs] = sv; bk2[rs] = kg; }
                }
        __syncthreads();
    }
#pragma unroll
    for (int rs = 0; rs < 4; rs++) {
        int r = wm * 32 + (rs >> 1) * 16 + gid + 8 * (rs & 1);
        unsigned long long pk = ((unsigned long long)mono(bd1[rs]) << 32) | (unsigned)bk1[rs];
        atomicMin(&sBest[r], pk);
    }
    __syncthreads();
#pragma unroll
    for (int rs = 0; rs < 4; rs++) {
        int r = wm * 32 + (rs >> 1) * 16 + gid + 8 * (rs & 1);
        // sound window: 2x per-score fp16 bound (3.05e-5*||z||) + fp32 slack
        float thr = demono((uint32_t)(sBest[r] >> 32))
                  + 7e-5f * sqrtf(g_sz[m0 + r]) + 1.5e-4f;
        if (bd1[rs] <= thr) {
            unsigned o = atomicAdd(&sCnt[r], 1u);
            if (o < CAP) sList[r * CAP + o] = bk1[rs];
        }
        if (bd2[rs] <= thr) {   // thread's top-2 both in window: unsafe token
            unsigned o = atomicAdd(&sCnt[r], 1u);
            if (o < CAP) sList[r * CAP + o] = bk2[rs];
            sFlg[r] = 1u;
        }
    }
    __syncthreads();
    if (tid < 64) {
        int n = m0 + tid; unsigned nc = sCnt[tid];
        if (sFlg[tid] || nc > CAP) {
            int p = atomicAdd(&g_nflag, 1); g_flag[p] = n; g_ncand[n] = -1;
        } else {
            g_ncand[n] = (int)nc;
            for (unsigned i = 0; i < nc; i++) g_cand[n * CAP + i] = sList[tid * CAP + i];
        }
    }
}

// ---- pass 2: exact rescore of candidates (R1-proven comparator) ------------
__global__ __launch_bounds__(256) void k_rescore(const float* __restrict__ z,
                                                 const float* __restrict__ emb) {
    extern __shared__ float zs[];   // [64][257]
    int tid = threadIdx.x;
    int m0 = blockIdx.x * 64;
    int bz = m0 >> 12, hw0 = m0 & (HW - 1);
    const float* zb = z + (size_t)bz * D * HW + hw0;
#pragma unroll 4
    for (int i = 0; i < 64; i++) {
        int id = i * 256 + tid;
        int d = id >> 6, r = id & 63;
        zs[r * 257 + d] = zb[(size_t)d * HW + r];
    }
    __syncthreads();
    if (tid < 64) {
        int n = m0 + tid;
        int nc = g_ncand[n];
        if (nc >= 0) {
            float szn = g_sz[n];
            const float* zr = zs + tid * 257;
            float best = 3.4e38f; int bk = 0x7fffffff;
            for (int i = 0; i < nc; i++) {
                int k = g_cand[n * CAP + i];
                const float* er = emb + (size_t)k * D;
                float a = 0.f;
                for (int d = 0; d < D; d++) a = fmaf(zr[d], er[d], a);
                float s1 = szn + g_en[k];
                float dv = fmaf(-2.f, a, s1);
                if (dv < best || (dv == best && k < bk)) { best = dv; bk = k; }
            }
            g_idx[n] = bk;
        }
    }
}

// ---- fallback: exact full scan, 16 flagged tokens per chunk (shared emb) ---
__global__ __launch_bounds__(256) void k_fb(const float* __restrict__ z,
                                            const float* __restrict__ emb) {
    __shared__ float zt[16][257];
    __shared__ unsigned long long red[16];
    int tid = threadIdx.x;
    int nf = g_nflag;
    int nchunk = (nf + 15) >> 4;
    for (int ch = blockIdx.x; ch < nchunk; ch += gridDim.x) {
        int base = ch * 16;
        int cnt = min(16, nf - base);
        if (tid < 16) red[tid] = ~0ull;
        __syncthreads();
#pragma unroll
        for (int i = 0; i < 16; i++) {
            int id = i * 256 + tid;
            int t = id >> 8, d = id & 255;
            if (t < cnt) {
                int n = g_flag[base + t];
                int bz = n >> 12, hw = n & (HW - 1);
                zt[t][d] = z[((size_t)bz * D + d) * HW + hw];
            }
        }
        __syncthreads();
#pragma unroll
        for (int j = 0; j < 4; j++) {
            int k = tid + 256 * j;
            const float* er = emb + (size_t)k * D;
            float acc[16];
#pragma unroll
            for (int t = 0; t < 16; t++) acc[t] = 0.f;
            for (int d = 0; d < D; d++) {
                float e = er[d];
#pragma unroll
                for (int t = 0; t < 16; t++) acc[t] = fmaf(zt[t][d], e, acc[t]);
            }
            for (int t = 0; t < cnt; t++) {
                int n = g_flag[base + t];
                float s1 = g_sz[n] + g_en[k];
                float dv = fmaf(-2.f, acc[t], s1);
                unsigned long long pk =
                    ((unsigned long long)mono(dv) << 32) | (unsigned)k;
                atomicMin(&red[t], pk);
            }
        }
        __syncthreads();
        if (tid < cnt) g_idx[g_flag[base + tid]] = (int)(red[tid] & 0xffffffffu);
        __syncthreads();
    }
}

// ---- outputs ----------------------------------------------------------------
__global__ void k_out_idx(float* __restrict__ out) {
    int n = blockIdx.x * blockDim.x + threadIdx.x;
    out[n] = (float)g_idx[n];
}
__global__ void k_out_zq(const float* __restrict__ emb, float* __restrict__ out) {
    int t = blockIdx.x * blockDim.x + threadIdx.x;
    int hw = t & (HW - 1);
    int c = (t >> 12) & (D - 1);
    int b = t >> 20;
    out[t] = emb[g_idx[b * HW + hw] * D + c];
}

extern "C" void kernel_launch(void* const* d_in, const int* in_sizes, int n_in,
                              void* d_out, int out_size) {
    const float* z   = (const float*)d_in[0];
    const float* emb = (const float*)d_in[1];
    float* out = (float*)d_out;

    cudaFuncSetAttribute(k_pass1, cudaFuncAttributeMaxDynamicSharedMemorySize, SM1);
    cudaFuncSetAttribute(k_rescore, cudaFuncAttributeMaxDynamicSharedMemorySize, 64 * 257 * 4);

    k_init<<<1, 32>>>();
    k_sz<<<N_TOK / 256, 256>>>(z);
    k_en<<<K / 8, 256>>>(emb);
    k_prep<<<K * D / 256, 256>>>(emb);
    k_pass1<<<N_TOK / 64, 256, SM1>>>(z);
    k_rescore<<<N_TOK / 64, 256, 64 * 257 * 4>>>(z, emb);
    k_fb<<<128, 256>>>(z, emb);
    k_out_idx<<<N_TOK / 256, 256>>>(out);
    k_out_zq<<<(16 * D * HW) / 256, 256>>>(emb, out + N_TOK);
}